// round 2
// baseline (speedup 1.0000x reference)
#include <cuda_runtime.h>
#include <math.h>

#define B 64
#define S 2048
#define E 1024
#define H 512
#define EMBD 256
#define V 50257
#define MTOT (B*S)

#define OUT_HT ((size_t)B*V)
#define OUT_CT (OUT_HT + (size_t)B*H)

// ---------------- device scratch (no allocations allowed) ----------------
__device__ float g_ws_app[B*H];        // h0@ws_w.T + ws_b + wh_b
__device__ float g_energy[MTOT];
__device__ float g_attn[MTOT];
__device__ float g_context[B*E];
__device__ float g_embed[B*EMBD];
__device__ float g_gates[B*4*H];
__device__ float g_logits[(size_t)B*V];
__device__ float g_pgen[B];

__device__ __forceinline__ float sigf(float x){ return 1.f/(1.f+__expf(-x)); }

// ---------------- 1) zero scratch that is accumulated via atomics --------
__global__ void zero_kernel(){
    int i = blockIdx.x*blockDim.x + threadIdx.x;
    if (i < MTOT) g_energy[i] = 0.f;
    if (i < B*E)  g_context[i] = 0.f;
}

// ---------------- 2) ws_app[b,n] = h0[b]·ws_w[n] + ws_b[n] + wh_b[n] -----
__global__ void wsapp_kernel(const float* __restrict__ h0,
                             const float* __restrict__ ws_w,
                             const float* __restrict__ ws_b,
                             const float* __restrict__ wh_b){
    int b = blockIdx.x;
    int warp = threadIdx.x >> 5, lane = threadIdx.x & 31;
    int n = blockIdx.y * 8 + warp;           // grid.y = 64 -> 512 n
    const float* wrow = ws_w + (size_t)n*H;
    const float* hrow = h0 + b*H;
    float acc = 0.f;
    for (int k = lane; k < H; k += 32) acc += hrow[k]*wrow[k];
    #pragma unroll
    for (int o = 16; o > 0; o >>= 1) acc += __shfl_xor_sync(0xffffffffu, acc, o);
    if (lane == 0) g_ws_app[b*H + n] = acc + ws_b[n] + wh_b[n];
}

// ---------------- 3) embedding lookup ------------------------------------
__global__ void embed_kernel(const int* __restrict__ dec_input,
                             const float* __restrict__ table){
    int b = blockIdx.x, t = threadIdx.x;     // 256 threads == EMBD
    g_embed[b*EMBD + t] = table[(size_t)dec_input[b]*EMBD + t];
}

// ---------------- 4) fused energy GEMM -----------------------------------
// energy[m] += sum_n tanh( enc[m]·wh_w[n] + ws_app[b,n] ) * attn_v[n]
// Tile 128x128x8, 256 threads, 8x8 microtiles.
__global__ __launch_bounds__(256) void energy_gemm(
        const float* __restrict__ enc,       // [M, E]
        const float* __restrict__ wh_w,      // [H, E]
        const float* __restrict__ attn_v){   // [H]
    __shared__ float As[8][128];
    __shared__ float Bs[8][128];
    const int m0 = blockIdx.x * 128;
    const int n0 = blockIdx.y * 128;
    const int tid = threadIdx.x;
    const int tx = tid & 15;
    const int ty = tid >> 4;
    const int lrow = tid >> 1;
    const int lcol = (tid & 1) << 2;
    const float* Ag = enc  + (size_t)(m0 + lrow)*E + lcol;
    const float* Bg = wh_w + (size_t)(n0 + lrow)*E + lcol;
    float acc[8][8];
    #pragma unroll
    for (int i = 0; i < 8; i++)
        #pragma unroll
        for (int j = 0; j < 8; j++) acc[i][j] = 0.f;

    for (int k0 = 0; k0 < E; k0 += 8) {
        float4 a  = *(const float4*)(Ag + k0);
        float4 bv = *(const float4*)(Bg + k0);
        As[lcol+0][lrow]=a.x;  As[lcol+1][lrow]=a.y;  As[lcol+2][lrow]=a.z;  As[lcol+3][lrow]=a.w;
        Bs[lcol+0][lrow]=bv.x; Bs[lcol+1][lrow]=bv.y; Bs[lcol+2][lrow]=bv.z; Bs[lcol+3][lrow]=bv.w;
        __syncthreads();
        #pragma unroll
        for (int kk = 0; kk < 8; kk++){
            float4 a0 = *(const float4*)(&As[kk][ty*8]);
            float4 a1 = *(const float4*)(&As[kk][ty*8+4]);
            float4 b0 = *(const float4*)(&Bs[kk][tx*8]);
            float4 b1 = *(const float4*)(&Bs[kk][tx*8+4]);
            float ra[8] = {a0.x,a0.y,a0.z,a0.w,a1.x,a1.y,a1.z,a1.w};
            float rb[8] = {b0.x,b0.y,b0.z,b0.w,b1.x,b1.y,b1.z,b1.w};
            #pragma unroll
            for (int i = 0; i < 8; i++)
                #pragma unroll
                for (int j = 0; j < 8; j++) acc[i][j] = fmaf(ra[i], rb[j], acc[i][j]);
        }
        __syncthreads();
    }
    // epilogue: tanh + dot with attn_v, reduce over the 16 tx columns
    const int b = m0 >> 11;                  // 128-row tiles never straddle a batch (2048%128==0)
    float wsn[8], vn[8];
    #pragma unroll
    for (int j = 0; j < 8; j++){
        int n = n0 + tx*8 + j;
        wsn[j] = g_ws_app[b*H + n];
        vn[j]  = attn_v[n];
    }
    #pragma unroll
    for (int i = 0; i < 8; i++){
        float p = 0.f;
        #pragma unroll
        for (int j = 0; j < 8; j++) p += tanhf(acc[i][j] + wsn[j]) * vn[j];
        p += __shfl_xor_sync(0xffffffffu, p, 8);
        p += __shfl_xor_sync(0xffffffffu, p, 4);
        p += __shfl_xor_sync(0xffffffffu, p, 2);
        p += __shfl_xor_sync(0xffffffffu, p, 1);
        if (tx == 0) atomicAdd(&g_energy[m0 + ty*8 + i], p);
    }
}

// ---------------- 5) softmax over S per batch ----------------------------
__global__ void attn_softmax(){
    const int b = blockIdx.x, t = threadIdx.x;   // 256 threads
    __shared__ float red[8];
    const float* e = g_energy + b*S;
    float m = -1e30f;
    for (int i = t; i < S; i += 256) m = fmaxf(m, e[i]);
    #pragma unroll
    for (int o = 16; o > 0; o >>= 1) m = fmaxf(m, __shfl_xor_sync(0xffffffffu, m, o));
    if ((t & 31) == 0) red[t >> 5] = m;
    __syncthreads();
    if (t == 0){ float mm = red[0]; for (int i = 1; i < 8; i++) mm = fmaxf(mm, red[i]); red[0] = mm; }
    __syncthreads();
    m = red[0];
    __syncthreads();
    float s = 0.f;
    for (int i = t; i < S; i += 256){ float x = __expf(e[i]-m); g_attn[b*S+i] = x; s += x; }
    #pragma unroll
    for (int o = 16; o > 0; o >>= 1) s += __shfl_xor_sync(0xffffffffu, s, o);
    if ((t & 31) == 0) red[t >> 5] = s;
    __syncthreads();
    if (t == 0){ float ss = 0.f; for (int i = 0; i < 8; i++) ss += red[i]; red[0] = ss; }
    __syncthreads();
    float inv = 1.f / red[0];
    for (int i = t; i < S; i += 256) g_attn[b*S+i] *= inv;
}

// ---------------- 6) context[b,e] = sum_s attn[b,s]*enc[b,s,e] -----------
__global__ void context_kernel(const float* __restrict__ enc){
    const int b = blockIdx.x, ec = blockIdx.y, sc = blockIdx.z;
    __shared__ float a_s[512];
    const int t = threadIdx.x;               // 256
    for (int i = t; i < 512; i += 256) a_s[i] = g_attn[b*S + sc*512 + i];
    __syncthreads();
    const int e = ec*256 + t;
    const float* base = enc + ((size_t)b*S + sc*512)*E + e;
    float acc = 0.f;
    #pragma unroll 4
    for (int s = 0; s < 512; s++) acc = fmaf(a_s[s], base[(size_t)s*E], acc);
    atomicAdd(&g_context[b*E + e], acc);
}

// ---------------- 7) LSTM gates GEMM: [ctx|emb|h0](64x1792) @ Wcat.T -----
__global__ __launch_bounds__(256) void gates_gemm(
        const float* __restrict__ h0,
        const float* __restrict__ w_ih,   // [2048, 1280]
        const float* __restrict__ w_hh,   // [2048, 512]
        const float* __restrict__ b_ih,
        const float* __restrict__ b_hh){
    __shared__ float Xs[16][65];
    __shared__ float Ws[16][65];
    const int n0 = blockIdx.x * 64;
    const int tid = threadIdx.x;
    const int tx = tid & 15, ty = tid >> 4;
    float acc[4][4];
    #pragma unroll
    for (int i = 0; i < 4; i++)
        #pragma unroll
        for (int j = 0; j < 4; j++) acc[i][j] = 0.f;

    for (int k0 = 0; k0 < 1792; k0 += 16) {
        for (int i = tid; i < 64*16; i += 256){
            int m = i >> 4, kk = i & 15, k = k0 + kk;
            float xv;
            if (k < E)            xv = g_context[m*E + k];
            else if (k < E+EMBD)  xv = g_embed[m*EMBD + (k - E)];
            else                  xv = h0[m*H + (k - E - EMBD)];
            Xs[kk][m] = xv;
        }
        for (int i = tid; i < 64*16; i += 256){
            int nn = i >> 4, kk = i & 15, k = k0 + kk, n = n0 + nn;
            float wv = (k < E+EMBD) ? w_ih[(size_t)n*(E+EMBD) + k]
                                    : w_hh[(size_t)n*H + (k - E - EMBD)];
            Ws[kk][nn] = wv;
        }
        __syncthreads();
        #pragma unroll
        for (int kk = 0; kk < 16; kk++){
            float ra[4], rb[4];
            #pragma unroll
            for (int i = 0; i < 4; i++) ra[i] = Xs[kk][ty*4+i];
            #pragma unroll
            for (int j = 0; j < 4; j++) rb[j] = Ws[kk][tx*4+j];
            #pragma unroll
            for (int i = 0; i < 4; i++)
                #pragma unroll
                for (int j = 0; j < 4; j++) acc[i][j] = fmaf(ra[i], rb[j], acc[i][j]);
        }
        __syncthreads();
    }
    #pragma unroll
    for (int i = 0; i < 4; i++)
        #pragma unroll
        for (int j = 0; j < 4; j++){
            int m = ty*4+i, n = n0 + tx*4+j;
            g_gates[m*(4*H) + n] = acc[i][j] + b_ih[n] + b_hh[n];
        }
}

// ---------------- 8) LSTM pointwise -> h_t, c_t into d_out ---------------
__global__ void lstm_kernel(const float* __restrict__ c0, float* __restrict__ out){
    const int b = blockIdx.x, h = threadIdx.x;   // 512
    const float* g = g_gates + b*(4*H);
    float ig = sigf(g[h]);
    float fg = sigf(g[H + h]);
    float gg = tanhf(g[2*H + h]);
    float og = sigf(g[3*H + h]);
    float c  = fg * c0[b*H + h] + ig * gg;
    float ht = og * tanhf(c);
    out[OUT_HT + b*H + h] = ht;
    out[OUT_CT + b*H + h] = c;
}

// ---------------- 9) logits = h_t @ v_w.T + v_b --------------------------
// Tile: 64(b) x 128(v) x 32(k), 256 threads, 4x8 microtiles.
__global__ __launch_bounds__(256) void logits_gemm(
        const float* __restrict__ ht,      // [B, H] (inside d_out)
        const float* __restrict__ v_w,     // [V, H]
        const float* __restrict__ v_b){
    __shared__ float Hs[32][64];
    __shared__ float Vs[32][128];
    const int v0 = blockIdx.x * 128;
    const int tid = threadIdx.x;
    const int tx = tid & 15, ty = tid >> 4;
    float acc[4][8];
    #pragma unroll
    for (int i = 0; i < 4; i++)
        #pragma unroll
        for (int j = 0; j < 8; j++) acc[i][j] = 0.f;

    for (int k0 = 0; k0 < H; k0 += 32) {
        // Hs: 64 x 32 = 512 float4
        for (int fl = tid; fl < 512; fl += 256){
            int m = fl >> 3, kq = (fl & 7) << 2;
            float4 hv = *(const float4*)(ht + (size_t)m*H + k0 + kq);
            Hs[kq+0][m]=hv.x; Hs[kq+1][m]=hv.y; Hs[kq+2][m]=hv.z; Hs[kq+3][m]=hv.w;
        }
        // Vs: 128 x 32 = 1024 float4 (guard v < V)
        for (int fl = tid; fl < 1024; fl += 256){
            int vr = fl >> 3, kq = (fl & 7) << 2;
            int v = v0 + vr;
            float4 wv = make_float4(0.f,0.f,0.f,0.f);
            if (v < V) wv = *(const float4*)(v_w + (size_t)v*H + k0 + kq);
            Vs[kq+0][vr]=wv.x; Vs[kq+1][vr]=wv.y; Vs[kq+2][vr]=wv.z; Vs[kq+3][vr]=wv.w;
        }
        __syncthreads();
        #pragma unroll
        for (int kk = 0; kk < 32; kk++){
            float4 a0 = *(const float4*)(&Hs[kk][ty*4]);
            float4 b0 = *(const float4*)(&Vs[kk][tx*8]);
            float4 b1 = *(const float4*)(&Vs[kk][tx*8+4]);
            float ra[4] = {a0.x,a0.y,a0.z,a0.w};
            float rb[8] = {b0.x,b0.y,b0.z,b0.w,b1.x,b1.y,b1.z,b1.w};
            #pragma unroll
            for (int i = 0; i < 4; i++)
                #pragma unroll
                for (int j = 0; j < 8; j++) acc[i][j] = fmaf(ra[i], rb[j], acc[i][j]);
        }
        __syncthreads();
    }
    #pragma unroll
    for (int i = 0; i < 4; i++)
        #pragma unroll
        for (int j = 0; j < 8; j++){
            int m = ty*4+i, v = v0 + tx*8+j;
            if (v < V) g_logits[(size_t)m*V + v] = acc[i][j] + v_b[v];
        }
}

// ---------------- 10) p_gen ----------------------------------------------
__global__ void pgen_kernel(const float* __restrict__ ht,
                            const float* __restrict__ wh_vec,
                            const float* __restrict__ ws_vec,
                            const float* __restrict__ wx_vec){
    const int b = blockIdx.x, t = threadIdx.x;    // 256
    __shared__ float red[8];
    float acc = 0.f;
    for (int i = t; i < E;    i += 256) acc += g_context[b*E + i]   * wh_vec[i];
    for (int i = t; i < H;    i += 256) acc += ht[b*H + i]          * ws_vec[i];
    for (int i = t; i < EMBD; i += 256) acc += g_embed[b*EMBD + i]  * wx_vec[i];
    #pragma unroll
    for (int o = 16; o > 0; o >>= 1) acc += __shfl_xor_sync(0xffffffffu, acc, o);
    if ((t & 31) == 0) red[t >> 5] = acc;
    __syncthreads();
    if (t == 0){
        float s = 0.f;
        for (int i = 0; i < 8; i++) s += red[i];
        g_pgen[b] = sigf(s);
    }
}

// ---------------- 11) vocab softmax * p_gen -> out -----------------------
__global__ void vocab_out_kernel(float* __restrict__ out){
    const int b = blockIdx.x, t = threadIdx.x;    // 512 threads
    __shared__ float red[16];
    const float* row = g_logits + (size_t)b*V;
    float m = -1e30f;
    for (int v = t; v < V; v += 512) m = fmaxf(m, row[v]);
    #pragma unroll
    for (int o = 16; o > 0; o >>= 1) m = fmaxf(m, __shfl_xor_sync(0xffffffffu, m, o));
    if ((t & 31) == 0) red[t >> 5] = m;
    __syncthreads();
    if (t == 0){ float mm = red[0]; for (int i = 1; i < 16; i++) mm = fmaxf(mm, red[i]); red[0] = mm; }
    __syncthreads();
    m = red[0];
    __syncthreads();
    float s = 0.f;
    for (int v = t; v < V; v += 512) s += __expf(row[v]-m);
    #pragma unroll
    for (int o = 16; o > 0; o >>= 1) s += __shfl_xor_sync(0xffffffffu, s, o);
    if ((t & 31) == 0) red[t >> 5] = s;
    __syncthreads();
    if (t == 0){ float ss = 0.f; for (int i = 0; i < 16; i++) ss += red[i]; red[0] = ss; }
    __syncthreads();
    const float scale = g_pgen[b] / red[0];
    for (int v = t; v < V; v += 512) out[(size_t)b*V + v] = __expf(row[v]-m) * scale;
}

// ---------------- 12) copy-mechanism scatter -----------------------------
__global__ void scatter_kernel(const int* __restrict__ enc_inputs,
                               float* __restrict__ out){
    const int idx = blockIdx.x*256 + threadIdx.x;
    if (idx >= MTOT) return;
    const int b = idx >> 11;
    const int tok = enc_inputs[idx];
    atomicAdd(&out[(size_t)b*V + tok], (1.f - g_pgen[b]) * g_attn[idx]);
}

// ---------------- launch --------------------------------------------------
extern "C" void kernel_launch(void* const* d_in, const int* in_sizes, int n_in,
                              void* d_out, int out_size) {
    const float* enc_out   = (const float*)d_in[0];
    const float* h0        = (const float*)d_in[1];
    const float* c0        = (const float*)d_in[2];
    const int*   dec_input = (const int*)  d_in[3];
    const int*   enc_inputs= (const int*)  d_in[4];
    const float* embed_tab = (const float*)d_in[5];
    const float* attn_wh_w = (const float*)d_in[6];
    const float* attn_wh_b = (const float*)d_in[7];
    const float* attn_ws_w = (const float*)d_in[8];
    const float* attn_ws_b = (const float*)d_in[9];
    const float* attn_v    = (const float*)d_in[10];
    const float* lstm_w_ih = (const float*)d_in[11];
    const float* lstm_w_hh = (const float*)d_in[12];
    const float* lstm_b_ih = (const float*)d_in[13];
    const float* lstm_b_hh = (const float*)d_in[14];
    const float* wh_vec    = (const float*)d_in[15];
    const float* ws_vec    = (const float*)d_in[16];
    const float* wx_vec    = (const float*)d_in[17];
    const float* v_w       = (const float*)d_in[18];
    const float* v_b       = (const float*)d_in[19];
    float* out = (float*)d_out;
    const float* ht = out + OUT_HT;

    zero_kernel<<<512, 256>>>();
    wsapp_kernel<<<dim3(B, 64), 256>>>(h0, attn_ws_w, attn_ws_b, attn_wh_b);
    embed_kernel<<<B, 256>>>(dec_input, embed_tab);
    energy_gemm<<<dim3(MTOT/128, H/128), 256>>>(enc_out, attn_wh_w, attn_v);
    attn_softmax<<<B, 256>>>();
    context_kernel<<<dim3(B, 4, 4), 256>>>(enc_out);
    gates_gemm<<<(4*H)/64, 256>>>(h0, lstm_w_ih, lstm_w_hh, lstm_b_ih, lstm_b_hh);
    lstm_kernel<<<B, 512>>>(c0, out);
    logits_gemm<<<(V + 127)/128, 256>>>(ht, v_w, v_b);
    pgen_kernel<<<B, 256>>>(ht, wh_vec, ws_vec, wx_vec);
    vocab_out_kernel<<<B, 512>>>(out);
    scatter_kernel<<<(MTOT + 255)/256, 256>>>(enc_inputs, out);
}

// round 5
// speedup vs baseline: 1.8476x; 1.8476x over previous
#include <cuda_runtime.h>
#include <cuda_bf16.h>
#include <math.h>
#include <stdint.h>

#define B 64
#define S 2048
#define E 1024
#define H 512
#define EMBD 256
#define V 50257
#define MTOT (B*S)

#define OUT_HT ((size_t)B*V)
#define OUT_CT (OUT_HT + (size_t)B*H)

// ---------------- device scratch (no allocations allowed) ----------------
__device__ float g_ws_app[B*H];        // h0@ws_w.T + ws_b + wh_b
__device__ float g_energy[MTOT];
__device__ float g_attn[MTOT];
__device__ float g_context[B*E];
__device__ float g_embed[B*EMBD];
__device__ float g_gates[B*4*H];
__device__ float g_logits[(size_t)B*V];
__device__ float g_pgen[B];

// split-bf16 copies of enc_out and attn_wh_w
__device__ __nv_bfloat16 g_enc_hi[(size_t)MTOT*E];
__device__ __nv_bfloat16 g_enc_lo[(size_t)MTOT*E];
__device__ __nv_bfloat16 g_w_hi[H*E];
__device__ __nv_bfloat16 g_w_lo[H*E];

__device__ __forceinline__ float sigf(float x){ return 1.f/(1.f+__expf(-x)); }

// ======================= portable PTX helpers =============================
__device__ __forceinline__ uint32_t smem_u32(const void* p){
    uint32_t a;
    asm("{ .reg .u64 t; cvta.to.shared.u64 t, %1; cvt.u32.u64 %0, t; }" : "=r"(a) : "l"(p));
    return a;
}
__device__ __forceinline__ void cp16(uint32_t dst, const void* src){
    asm volatile("cp.async.cg.shared.global [%0], [%1], 16;" :: "r"(dst), "l"(src));
}
__device__ __forceinline__ void cp_commit(){ asm volatile("cp.async.commit_group;" ::: "memory"); }
__device__ __forceinline__ void cp_wait0(){ asm volatile("cp.async.wait_group 0;" ::: "memory"); }
__device__ __forceinline__ void cp_wait1(){ asm volatile("cp.async.wait_group 1;" ::: "memory"); }

__device__ __forceinline__ void ldsm4(uint32_t* r, uint32_t addr){
    asm volatile("ldmatrix.sync.aligned.m8n8.x4.shared.b16 {%0,%1,%2,%3}, [%4];"
        : "=r"(r[0]), "=r"(r[1]), "=r"(r[2]), "=r"(r[3]) : "r"(addr));
}
__device__ __forceinline__ void mma16816(float* c, const uint32_t* a, uint32_t b0, uint32_t b1){
    asm volatile("mma.sync.aligned.m16n8k16.row.col.f32.bf16.bf16.f32 "
        "{%0,%1,%2,%3}, {%4,%5,%6,%7}, {%8,%9}, {%0,%1,%2,%3};"
        : "+f"(c[0]), "+f"(c[1]), "+f"(c[2]), "+f"(c[3])
        : "r"(a[0]), "r"(a[1]), "r"(a[2]), "r"(a[3]), "r"(b0), "r"(b1));
}

// ---------------- split-bf16 conversion kernels ---------------------------
__global__ void conv_enc_kernel(const float* __restrict__ src){
    size_t i = ((size_t)blockIdx.x*256 + threadIdx.x)*4;
    float4 v = *(const float4*)(src + i);
    __nv_bfloat16 h[4], l[4];
    float x[4] = {v.x, v.y, v.z, v.w};
    #pragma unroll
    for (int k = 0; k < 4; k++){
        h[k] = __float2bfloat16(x[k]);
        l[k] = __float2bfloat16(x[k] - __bfloat162float(h[k]));
    }
    *(uint2*)(g_enc_hi + i) = *(uint2*)h;
    *(uint2*)(g_enc_lo + i) = *(uint2*)l;
}
__global__ void conv_w_kernel(const float* __restrict__ src){
    int i = blockIdx.x*256 + threadIdx.x;
    float x = src[i];
    __nv_bfloat16 h = __float2bfloat16(x);
    g_w_hi[i] = h;
    g_w_lo[i] = __float2bfloat16(x - __bfloat162float(h));
}

// ---------------- 1) zero scratch accumulated via atomics ----------------
__global__ void zero_kernel(){
    int i = blockIdx.x*blockDim.x + threadIdx.x;
    if (i < MTOT) g_energy[i] = 0.f;
    if (i < B*E)  g_context[i] = 0.f;
}

// ---------------- 2) ws_app[b,n] = h0[b]·ws_w[n] + ws_b[n] + wh_b[n] -----
__global__ void wsapp_kernel(const float* __restrict__ h0,
                             const float* __restrict__ ws_w,
                             const float* __restrict__ ws_b,
                             const float* __restrict__ wh_b){
    int b = blockIdx.x;
    int warp = threadIdx.x >> 5, lane = threadIdx.x & 31;
    int n = blockIdx.y * 8 + warp;
    const float* wrow = ws_w + (size_t)n*H;
    const float* hrow = h0 + b*H;
    float acc = 0.f;
    for (int k = lane; k < H; k += 32) acc += hrow[k]*wrow[k];
    #pragma unroll
    for (int o = 16; o > 0; o >>= 1) acc += __shfl_xor_sync(0xffffffffu, acc, o);
    if (lane == 0) g_ws_app[b*H + n] = acc + ws_b[n] + wh_b[n];
}

// ---------------- 3) embedding lookup ------------------------------------
__global__ void embed_kernel(const int* __restrict__ dec_input,
                             const float* __restrict__ table){
    int b = blockIdx.x, t = threadIdx.x;
    g_embed[b*EMBD + t] = table[(size_t)dec_input[b]*EMBD + t];
}

// ---------------- 4) split-bf16 energy GEMM on HMMA (mma.sync) -----------
// energy[m] += sum_n tanh( (AhiBhi + AhiBlo + AloBhi)[m,n] + ws_app[b,n] ) * v[n]
#define MT 128
#define NTILE 128
#define KC 32
#define NCH (E/KC)                 // 32
#define ROWB 80                    // padded row stride in bytes (40 bf16)
#define ARRB (128*ROWB)            // 10240 bytes per tile array
#define STG_BYTES (4*ARRB)         // Ahi,Alo,Bhi,Blo
#define WS_OFF (2*STG_BYTES)
#define V_OFF  (WS_OFF + 512)
#define EN_SMEM (V_OFF + 512)

__global__ __launch_bounds__(256) void energy_mma(const float* __restrict__ attn_v){
    extern __shared__ char sm[];
    const int tid  = threadIdx.x;
    const int lane = tid & 31, wid = tid >> 5;
    const int wm = wid & 3;           // 4 M-groups of 32 rows
    const int wn = wid >> 2;          // 2 N-groups of 64 cols
    const int n0 = blockIdx.x * NTILE;
    const int m0 = blockIdx.y * MT;
    const int b  = m0 >> 11;

    float* wsP = (float*)(sm + WS_OFF);
    float* vP  = (float*)(sm + V_OFF);
    for (int j = tid; j < NTILE; j += 256){
        wsP[j] = g_ws_app[b*H + n0 + j];
        vP[j]  = attn_v[n0 + j];
    }

    const __nv_bfloat16* gsrc0 = g_enc_hi + (size_t)m0*E;
    const __nv_bfloat16* gsrc1 = g_enc_lo + (size_t)m0*E;
    const __nv_bfloat16* gsrc2 = g_w_hi  + (size_t)n0*E;
    const __nv_bfloat16* gsrc3 = g_w_lo  + (size_t)n0*E;
    const uint32_t smb = smem_u32(sm);

    auto load_stage = [&](int s, int k0){
        uint32_t stg = smb + s*STG_BYTES;
        #pragma unroll
        for (int it = 0; it < 8; it++){
            int f = tid + it*256;          // 0..2047
            int arr = f >> 9;              // 0..3
            int r   = (f >> 2) & 127;      // row
            int j   = f & 3;               // 16B chunk
            const __nv_bfloat16* src =
                (arr == 0 ? gsrc0 : arr == 1 ? gsrc1 : arr == 2 ? gsrc2 : gsrc3);
            cp16(stg + arr*ARRB + r*ROWB + j*16, src + (size_t)r*E + k0 + j*8);
        }
        cp_commit();
    };

    float c[2][8][4];
    #pragma unroll
    for (int t = 0; t < 2; t++)
        #pragma unroll
        for (int j = 0; j < 8; j++)
            #pragma unroll
            for (int q = 0; q < 4; q++) c[t][j][q] = 0.f;

    load_stage(0, 0);

    for (int i = 0; i < NCH; i++){
        if (i + 1 < NCH){ load_stage((i+1)&1, (i+1)*KC); cp_wait1(); }
        else            { cp_wait0(); }
        __syncthreads();

        const uint32_t stg = smb + (i&1)*STG_BYTES;
        const uint32_t A0 = stg, A1 = stg + ARRB, B0 = stg + 2*ARRB, B1 = stg + 3*ARRB;

        #pragma unroll
        for (int kk = 0; kk < 2; kk++){
            uint32_t ah[2][4], al[2][4];
            #pragma unroll
            for (int t = 0; t < 2; t++){
                int row = wm*32 + t*16 + (lane & 15);
                uint32_t off = (uint32_t)row*ROWB + (lane >> 4)*16 + kk*32;
                ldsm4(ah[t], A0 + off);
                ldsm4(al[t], A1 + off);
            }
            #pragma unroll
            for (int p = 0; p < 4; p++){
                int row = wn*64 + p*16 + ((lane >> 4) & 1)*8 + (lane & 7);
                uint32_t off = (uint32_t)row*ROWB + ((lane >> 3) & 1)*16 + kk*32;
                uint32_t rh[4], rl[4];
                ldsm4(rh, B0 + off);
                ldsm4(rl, B1 + off);
                #pragma unroll
                for (int t = 0; t < 2; t++){
                    mma16816(c[t][2*p],   ah[t], rh[0], rh[1]);
                    mma16816(c[t][2*p],   ah[t], rl[0], rl[1]);
                    mma16816(c[t][2*p],   al[t], rh[0], rh[1]);
                    mma16816(c[t][2*p+1], ah[t], rh[2], rh[3]);
                    mma16816(c[t][2*p+1], ah[t], rl[2], rl[3]);
                    mma16816(c[t][2*p+1], al[t], rh[2], rh[3]);
                }
            }
        }
        __syncthreads();
    }

    // epilogue: tanh + dot attn_v, reduce 4-lane groups, atomicAdd per row
    float p4[4] = {0.f, 0.f, 0.f, 0.f};
    #pragma unroll
    for (int t = 0; t < 2; t++)
        #pragma unroll
        for (int j = 0; j < 8; j++)
            #pragma unroll
            for (int q = 0; q < 4; q++){
                int nloc = wn*64 + j*8 + (lane & 3)*2 + (q & 1);
                float x = c[t][j][q] + wsP[nloc];
                p4[t*2 + (q >> 1)] += tanhf(x) * vP[nloc];
            }
    #pragma unroll
    for (int q = 0; q < 4; q++){
        p4[q] += __shfl_xor_sync(0xffffffffu, p4[q], 1);
        p4[q] += __shfl_xor_sync(0xffffffffu, p4[q], 2);
    }
    if ((lane & 3) == 0){
        int rbase = m0 + wm*32 + (lane >> 2);
        atomicAdd(&g_energy[rbase],      p4[0]);
        atomicAdd(&g_energy[rbase + 8],  p4[1]);
        atomicAdd(&g_energy[rbase + 16], p4[2]);
        atomicAdd(&g_energy[rbase + 24], p4[3]);
    }
}

// ---------------- 5) softmax over S per batch ----------------------------
__global__ void attn_softmax(){
    const int b = blockIdx.x, t = threadIdx.x;
    __shared__ float red[8];
    const float* e = g_energy + b*S;
    float m = -1e30f;
    for (int i = t; i < S; i += 256) m = fmaxf(m, e[i]);
    #pragma unroll
    for (int o = 16; o > 0; o >>= 1) m = fmaxf(m, __shfl_xor_sync(0xffffffffu, m, o));
    if ((t & 31) == 0) red[t >> 5] = m;
    __syncthreads();
    if (t == 0){ float mm = red[0]; for (int i = 1; i < 8; i++) mm = fmaxf(mm, red[i]); red[0] = mm; }
    __syncthreads();
    m = red[0];
    __syncthreads();
    float s = 0.f;
    for (int i = t; i < S; i += 256){ float x = __expf(e[i]-m); g_attn[b*S+i] = x; s += x; }
    #pragma unroll
    for (int o = 16; o > 0; o >>= 1) s += __shfl_xor_sync(0xffffffffu, s, o);
    if ((t & 31) == 0) red[t >> 5] = s;
    __syncthreads();
    if (t == 0){ float ss = 0.f; for (int i = 0; i < 8; i++) ss += red[i]; red[0] = ss; }
    __syncthreads();
    float inv = 1.f / red[0];
    for (int i = t; i < S; i += 256) g_attn[b*S+i] *= inv;
}

// ---------------- 6) context[b,e] = sum_s attn[b,s]*enc[b,s,e] -----------
__global__ void context_kernel(const float* __restrict__ enc){
    const int b = blockIdx.x, ec = blockIdx.y, sc = blockIdx.z;
    __shared__ float a_s[512];
    const int t = threadIdx.x;
    for (int i = t; i < 512; i += 256) a_s[i] = g_attn[b*S + sc*512 + i];
    __syncthreads();
    const int e = ec*256 + t;
    const float* base = enc + ((size_t)b*S + sc*512)*E + e;
    float acc = 0.f;
    #pragma unroll 4
    for (int s = 0; s < 512; s++) acc = fmaf(a_s[s], base[(size_t)s*E], acc);
    atomicAdd(&g_context[b*E + e], acc);
}

// ---------------- 7) LSTM gates GEMM -------------------------------------
__global__ __launch_bounds__(256) void gates_gemm(
        const float* __restrict__ h0,
        const float* __restrict__ w_ih,
        const float* __restrict__ w_hh,
        const float* __restrict__ b_ih,
        const float* __restrict__ b_hh){
    __shared__ float Xs[16][65];
    __shared__ float Ws[16][65];
    const int n0 = blockIdx.x * 64;
    const int tid = threadIdx.x;
    const int tx = tid & 15, ty = tid >> 4;
    float acc[4][4];
    #pragma unroll
    for (int i = 0; i < 4; i++)
        #pragma unroll
        for (int j = 0; j < 4; j++) acc[i][j] = 0.f;

    for (int k0 = 0; k0 < 1792; k0 += 16) {
        for (int i = tid; i < 64*16; i += 256){
            int m = i >> 4, kk = i & 15, k = k0 + kk;
            float xv;
            if (k < E)            xv = g_context[m*E + k];
            else if (k < E+EMBD)  xv = g_embed[m*EMBD + (k - E)];
            else                  xv = h0[m*H + (k - E - EMBD)];
            Xs[kk][m] = xv;
        }
        for (int i = tid; i < 64*16; i += 256){
            int nn = i >> 4, kk = i & 15, k = k0 + kk, n = n0 + nn;
            float wv = (k < E+EMBD) ? w_ih[(size_t)n*(E+EMBD) + k]
                                    : w_hh[(size_t)n*H + (k - E - EMBD)];
            Ws[kk][nn] = wv;
        }
        __syncthreads();
        #pragma unroll
        for (int kk = 0; kk < 16; kk++){
            float ra[4], rb[4];
            #pragma unroll
            for (int i = 0; i < 4; i++) ra[i] = Xs[kk][ty*4+i];
            #pragma unroll
            for (int j = 0; j < 4; j++) rb[j] = Ws[kk][tx*4+j];
            #pragma unroll
            for (int i = 0; i < 4; i++)
                #pragma unroll
                for (int j = 0; j < 4; j++) acc[i][j] = fmaf(ra[i], rb[j], acc[i][j]);
        }
        __syncthreads();
    }
    #pragma unroll
    for (int i = 0; i < 4; i++)
        #pragma unroll
        for (int j = 0; j < 4; j++){
            int m = ty*4+i, n = n0 + tx*4+j;
            g_gates[m*(4*H) + n] = acc[i][j] + b_ih[n] + b_hh[n];
        }
}

// ---------------- 8) LSTM pointwise --------------------------------------
__global__ void lstm_kernel(const float* __restrict__ c0, float* __restrict__ out){
    const int b = blockIdx.x, h = threadIdx.x;
    const float* g = g_gates + b*(4*H);
    float ig = sigf(g[h]);
    float fg = sigf(g[H + h]);
    float gg = tanhf(g[2*H + h]);
    float og = sigf(g[3*H + h]);
    float c  = fg * c0[b*H + h] + ig * gg;
    float ht = og * tanhf(c);
    out[OUT_HT + b*H + h] = ht;
    out[OUT_CT + b*H + h] = c;
}

// ---------------- 9) logits = h_t @ v_w.T + v_b --------------------------
__global__ __launch_bounds__(256) void logits_gemm(
        const float* __restrict__ ht,
        const float* __restrict__ v_w,
        const float* __restrict__ v_b){
    __shared__ float Hs[32][64];
    __shared__ float Vs[32][128];
    const int v0 = blockIdx.x * 128;
    const int tid = threadIdx.x;
    const int tx = tid & 15, ty = tid >> 4;
    float acc[4][8];
    #pragma unroll
    for (int i = 0; i < 4; i++)
        #pragma unroll
        for (int j = 0; j < 8; j++) acc[i][j] = 0.f;

    for (int k0 = 0; k0 < H; k0 += 32) {
        for (int fl = tid; fl < 512; fl += 256){
            int m = fl >> 3, kq = (fl & 7) << 2;
            float4 hv = *(const float4*)(ht + (size_t)m*H + k0 + kq);
            Hs[kq+0][m]=hv.x; Hs[kq+1][m]=hv.y; Hs[kq+2][m]=hv.z; Hs[kq+3][m]=hv.w;
        }
        for (int fl = tid; fl < 1024; fl += 256){
            int vr = fl >> 3, kq = (fl & 7) << 2;
            int v = v0 + vr;
            float4 wv = make_float4(0.f,0.f,0.f,0.f);
            if (v < V) wv = *(const float4*)(v_w + (size_t)v*H + k0 + kq);
            Vs[kq+0][vr]=wv.x; Vs[kq+1][vr]=wv.y; Vs[kq+2][vr]=wv.z; Vs[kq+3][vr]=wv.w;
        }
        __syncthreads();
        #pragma unroll
        for (int kk = 0; kk < 32; kk++){
            float4 a0 = *(const float4*)(&Hs[kk][ty*4]);
            float4 b0 = *(const float4*)(&Vs[kk][tx*8]);
            float4 b1 = *(const float4*)(&Vs[kk][tx*8+4]);
            float ra[4] = {a0.x,a0.y,a0.z,a0.w};
            float rb[8] = {b0.x,b0.y,b0.z,b0.w,b1.x,b1.y,b1.z,b1.w};
            #pragma unroll
            for (int i = 0; i < 4; i++)
                #pragma unroll
                for (int j = 0; j < 8; j++) acc[i][j] = fmaf(ra[i], rb[j], acc[i][j]);
        }
        __syncthreads();
    }
    #pragma unroll
    for (int i = 0; i < 4; i++)
        #pragma unroll
        for (int j = 0; j < 8; j++){
            int m = ty*4+i, v = v0 + tx*8+j;
            if (v < V) g_logits[(size_t)m*V + v] = acc[i][j] + v_b[v];
        }
}

// ---------------- 10) p_gen ----------------------------------------------
__global__ void pgen_kernel(const float* __restrict__ ht,
                            const float* __restrict__ wh_vec,
                            const float* __restrict__ ws_vec,
                            const float* __restrict__ wx_vec){
    const int b = blockIdx.x, t = threadIdx.x;
    __shared__ float red[8];
    float acc = 0.f;
    for (int i = t; i < E;    i += 256) acc += g_context[b*E + i]   * wh_vec[i];
    for (int i = t; i < H;    i += 256) acc += ht[b*H + i]          * ws_vec[i];
    for (int i = t; i < EMBD; i += 256) acc += g_embed[b*EMBD + i]  * wx_vec[i];
    #pragma unroll
    for (int o = 16; o > 0; o >>= 1) acc += __shfl_xor_sync(0xffffffffu, acc, o);
    if ((t & 31) == 0) red[t >> 5] = acc;
    __syncthreads();
    if (t == 0){
        float s = 0.f;
        for (int i = 0; i < 8; i++) s += red[i];
        g_pgen[b] = sigf(s);
    }
}

// ---------------- 11) vocab softmax * p_gen -> out -----------------------
__global__ void vocab_out_kernel(float* __restrict__ out){
    const int b = blockIdx.x, t = threadIdx.x;
    __shared__ float red[16];
    const float* row = g_logits + (size_t)b*V;
    float m = -1e30f;
    for (int v = t; v < V; v += 512) m = fmaxf(m, row[v]);
    #pragma unroll
    for (int o = 16; o > 0; o >>= 1) m = fmaxf(m, __shfl_xor_sync(0xffffffffu, m, o));
    if ((t & 31) == 0) red[t >> 5] = m;
    __syncthreads();
    if (t == 0){ float mm = red[0]; for (int i = 1; i < 16; i++) mm = fmaxf(mm, red[i]); red[0] = mm; }
    __syncthreads();
    m = red[0];
    __syncthreads();
    float s = 0.f;
    for (int v = t; v < V; v += 512) s += __expf(row[v]-m);
    #pragma unroll
    for (int o = 16; o > 0; o >>= 1) s += __shfl_xor_sync(0xffffffffu, s, o);
    if ((t & 31) == 0) red[t >> 5] = s;
    __syncthreads();
    if (t == 0){ float ss = 0.f; for (int i = 0; i < 16; i++) ss += red[i]; red[0] = ss; }
    __syncthreads();
    const float scale = g_pgen[b] / red[0];
    for (int v = t; v < V; v += 512) out[(size_t)b*V + v] = __expf(row[v]-m) * scale;
}

// ---------------- 12) copy-mechanism scatter -----------------------------
__global__ void scatter_kernel(const int* __restrict__ enc_inputs,
                               float* __restrict__ out){
    const int idx = blockIdx.x*256 + threadIdx.x;
    if (idx >= MTOT) return;
    const int b = idx >> 11;
    const int tok = enc_inputs[idx];
    atomicAdd(&out[(size_t)b*V + tok], (1.f - g_pgen[b]) * g_attn[idx]);
}

// ---------------- launch --------------------------------------------------
extern "C" void kernel_launch(void* const* d_in, const int* in_sizes, int n_in,
                              void* d_out, int out_size) {
    const float* enc_out   = (const float*)d_in[0];
    const float* h0        = (const float*)d_in[1];
    const float* c0        = (const float*)d_in[2];
    const int*   dec_input = (const int*)  d_in[3];
    const int*   enc_inputs= (const int*)  d_in[4];
    const float* embed_tab = (const float*)d_in[5];
    const float* attn_wh_w = (const float*)d_in[6];
    const float* attn_wh_b = (const float*)d_in[7];
    const float* attn_ws_w = (const float*)d_in[8];
    const float* attn_ws_b = (const float*)d_in[9];
    const float* attn_v    = (const float*)d_in[10];
    const float* lstm_w_ih = (const float*)d_in[11];
    const float* lstm_w_hh = (const float*)d_in[12];
    const float* lstm_b_ih = (const float*)d_in[13];
    const float* lstm_b_hh = (const float*)d_in[14];
    const float* wh_vec    = (const float*)d_in[15];
    const float* ws_vec    = (const float*)d_in[16];
    const float* wx_vec    = (const float*)d_in[17];
    const float* v_w       = (const float*)d_in[18];
    const float* v_b       = (const float*)d_in[19];
    float* out = (float*)d_out;
    const float* ht = out + OUT_HT;

    static bool attr_set = false;
    if (!attr_set){
        cudaFuncSetAttribute(energy_mma, cudaFuncAttributeMaxDynamicSharedMemorySize, EN_SMEM);
        attr_set = true;
    }

    zero_kernel<<<512, 256>>>();
    conv_enc_kernel<<<131072, 256>>>(enc_out);
    conv_w_kernel<<<2048, 256>>>(attn_wh_w);
    wsapp_kernel<<<dim3(B, 64), 256>>>(h0, attn_ws_w, attn_ws_b, attn_wh_b);
    embed_kernel<<<B, 256>>>(dec_input, embed_tab);
    energy_mma<<<dim3(H/NTILE, MTOT/MT), 256, EN_SMEM>>>(attn_v);
    attn_softmax<<<B, 256>>>();
    context_kernel<<<dim3(B, 4, 4), 256>>>(enc_out);
    gates_gemm<<<(4*H)/64, 256>>>(h0, lstm_w_ih, lstm_w_hh, lstm_b_ih, lstm_b_hh);
    lstm_kernel<<<B, 512>>>(c0, out);
    logits_gemm<<<(V + 127)/128, 256>>>(ht, v_w, v_b);
    pgen_kernel<<<B, 256>>>(ht, wh_vec, ws_vec, wx_vec);
    vocab_out_kernel<<<B, 512>>>(out);
    scatter_kernel<<<(MTOT + 255)/256, 256>>>(enc_inputs, out);
}

// round 6
// speedup vs baseline: 2.2258x; 1.2047x over previous
#include <cuda_runtime.h>
#include <cuda_bf16.h>
#include <math.h>
#include <stdint.h>

#define B 64
#define S 2048
#define E 1024
#define H 512
#define EMBD 256
#define V 50257
#define MTOT (B*S)

#define OUT_HT ((size_t)B*V)
#define OUT_CT (OUT_HT + (size_t)B*H)

// ---------------- device scratch (no allocations allowed) ----------------
__device__ float g_ws_app[B*H];        // h0@ws_w.T + ws_b + wh_b
__device__ float g_energy4[4][MTOT];   // per-n-block energy partials
__device__ float g_energy[MTOT];       // combined (written by softmax pass 1)
__device__ float g_attn[MTOT];
__device__ float g_context[B*E];
__device__ float g_embed[B*EMBD];
__device__ float g_gates[B*4*H];
__device__ float g_logits[(size_t)B*V];
__device__ float g_pgen[B];

// split-bf16 copy of attn_wh_w only (enc_out converted in-kernel)
__device__ __nv_bfloat16 g_w_hi[H*E];
__device__ __nv_bfloat16 g_w_lo[H*E];

__device__ __forceinline__ float sigf(float x){ return 1.f/(1.f+__expf(-x)); }

// ======================= portable PTX helpers =============================
__device__ __forceinline__ uint32_t smem_u32(const void* p){
    uint32_t a;
    asm("{ .reg .u64 t; cvta.to.shared.u64 t, %1; cvt.u32.u64 %0, t; }" : "=r"(a) : "l"(p));
    return a;
}
__device__ __forceinline__ void cp16(uint32_t dst, const void* src){
    asm volatile("cp.async.cg.shared.global [%0], [%1], 16;" :: "r"(dst), "l"(src));
}
__device__ __forceinline__ void cp_commit(){ asm volatile("cp.async.commit_group;" ::: "memory"); }
__device__ __forceinline__ void cp_wait0(){ asm volatile("cp.async.wait_group 0;" ::: "memory"); }
__device__ __forceinline__ void cp_wait1(){ asm volatile("cp.async.wait_group 1;" ::: "memory"); }

__device__ __forceinline__ void ldsm4(uint32_t* r, uint32_t addr){
    asm volatile("ldmatrix.sync.aligned.m8n8.x4.shared.b16 {%0,%1,%2,%3}, [%4];"
        : "=r"(r[0]), "=r"(r[1]), "=r"(r[2]), "=r"(r[3]) : "r"(addr));
}
__device__ __forceinline__ void mma16816(float* c, const uint32_t* a, uint32_t b0, uint32_t b1){
    asm volatile("mma.sync.aligned.m16n8k16.row.col.f32.bf16.bf16.f32 "
        "{%0,%1,%2,%3}, {%4,%5,%6,%7}, {%8,%9}, {%0,%1,%2,%3};"
        : "+f"(c[0]), "+f"(c[1]), "+f"(c[2]), "+f"(c[3])
        : "r"(a[0]), "r"(a[1]), "r"(a[2]), "r"(a[3]), "r"(b0), "r"(b1));
}

// ---------------- split-bf16 conversion for weights -----------------------
__global__ void conv_w_kernel(const float* __restrict__ src){
    int i = blockIdx.x*256 + threadIdx.x;
    float x = src[i];
    __nv_bfloat16 h = __float2bfloat16(x);
    g_w_hi[i] = h;
    g_w_lo[i] = __float2bfloat16(x - __bfloat162float(h));
}

// ---------------- 1) zero context (accumulated via atomics) --------------
__global__ void zero_kernel(){
    int i = blockIdx.x*blockDim.x + threadIdx.x;
    if (i < B*E) g_context[i] = 0.f;
}

// ---------------- 2) ws_app[b,n] = h0[b]·ws_w[n] + ws_b[n] + wh_b[n] -----
__global__ void wsapp_kernel(const float* __restrict__ h0,
                             const float* __restrict__ ws_w,
                             const float* __restrict__ ws_b,
                             const float* __restrict__ wh_b){
    int b = blockIdx.x;
    int warp = threadIdx.x >> 5, lane = threadIdx.x & 31;
    int n = blockIdx.y * 8 + warp;
    const float* wrow = ws_w + (size_t)n*H;
    const float* hrow = h0 + b*H;
    float acc = 0.f;
    for (int k = lane; k < H; k += 32) acc += hrow[k]*wrow[k];
    #pragma unroll
    for (int o = 16; o > 0; o >>= 1) acc += __shfl_xor_sync(0xffffffffu, acc, o);
    if (lane == 0) g_ws_app[b*H + n] = acc + ws_b[n] + wh_b[n];
}

// ---------------- 3) embedding lookup ------------------------------------
__global__ void embed_kernel(const int* __restrict__ dec_input,
                             const float* __restrict__ table){
    int b = blockIdx.x, t = threadIdx.x;
    g_embed[b*EMBD + t] = table[(size_t)dec_input[b]*EMBD + t];
}

// ---------------- 4) split-bf16 energy GEMM on HMMA (mma.sync) -----------
// A (enc) read fp32 from global, split to bf16 hi/lo in-register, st.shared.
// energy[m] += sum_n tanh( (AhiBhi + AhiBlo + AloBhi)[m,n] + ws[b,n] ) * v[n]
#define MT 128
#define NTILE 128
#define KC 32
#define NCH (E/KC)                 // 32
#define ROWB 80                    // padded row stride in bytes (40 bf16)
#define ARRB (128*ROWB)            // 10240 bytes per tile array
#define STG_BYTES (4*ARRB)         // Ahi,Alo,Bhi,Blo per stage
#define WS_OFF (2*STG_BYTES)       // 81920
#define V_OFF  (WS_OFF + 512)
#define EN_SMEM (V_OFF + 512)

__global__ __launch_bounds__(256, 2) void energy_mma(
        const float* __restrict__ enc, const float* __restrict__ attn_v){
    extern __shared__ char sm[];
    const int tid  = threadIdx.x;
    const int lane = tid & 31, wid = tid >> 5;
    const int wm = wid & 3;           // 4 M-groups of 32 rows
    const int wn = wid >> 2;          // 2 N-groups of 64 cols
    const int n0 = blockIdx.x * NTILE;
    const int m0 = blockIdx.y * MT;
    const int b  = m0 >> 11;

    float* wsP = (float*)(sm + WS_OFF);
    float* vP  = (float*)(sm + V_OFF);
    for (int j = tid; j < NTILE; j += 256){
        wsP[j] = g_ws_app[b*H + n0 + j];
        vP[j]  = attn_v[n0 + j];
    }

    const uint32_t smb = smem_u32(sm);
    const __nv_bfloat16* Bhi_g = g_w_hi + (size_t)n0*E;
    const __nv_bfloat16* Blo_g = g_w_lo + (size_t)n0*E;

    // per-thread A mapping: row r, k-half kh (16 floats)
    const int ar = tid >> 1;
    const int kh = tid & 1;
    const float* Abase = enc + (size_t)(m0 + ar)*E + kh*16;

    // B cp.async for a stage
    auto loadB = [&](int stage, int k0){
        uint32_t stg = smb + (stage&1)*STG_BYTES;
        #pragma unroll
        for (int it = 0; it < 4; it++){
            int f = tid + it*256;          // 0..1023
            int arr = f >> 9;              // 0: hi, 1: lo
            int r   = (f >> 2) & 127;
            int j   = f & 3;
            const __nv_bfloat16* src = (arr ? Blo_g : Bhi_g) + (size_t)r*E + k0 + j*8;
            cp16(stg + (2+arr)*ARRB + r*ROWB + j*16, src);
        }
        cp_commit();
    };

    float areg[16];
    auto loadA = [&](int k0){
        const float4* gp = (const float4*)(Abase + k0);
        #pragma unroll
        for (int q = 0; q < 4; q++){
            float4 v = gp[q];
            areg[q*4+0] = v.x; areg[q*4+1] = v.y; areg[q*4+2] = v.z; areg[q*4+3] = v.w;
        }
    };
    auto storeA = [&](int stage){
        uint32_t stg = smb + (stage&1)*STG_BYTES;
        __nv_bfloat16 hb[16], lb[16];
        #pragma unroll
        for (int q = 0; q < 16; q++){
            hb[q] = __float2bfloat16(areg[q]);
            lb[q] = __float2bfloat16(areg[q] - __bfloat162float(hb[q]));
        }
        uint32_t off = (uint32_t)ar*ROWB + kh*32;
        *(uint4*)(sm + (stg - smb) + off)          = *(uint4*)&hb[0];
        *(uint4*)(sm + (stg - smb) + off + 16)     = *(uint4*)&hb[8];
        *(uint4*)(sm + (stg - smb) + ARRB + off)   = *(uint4*)&lb[0];
        *(uint4*)(sm + (stg - smb) + ARRB + off+16)= *(uint4*)&lb[8];
    };

    float c[2][8][4];
    #pragma unroll
    for (int t = 0; t < 2; t++)
        #pragma unroll
        for (int j = 0; j < 8; j++)
            #pragma unroll
            for (int q = 0; q < 4; q++) c[t][j][q] = 0.f;

    // prologue: B(0) in flight, A(0) in regs
    loadB(0, 0);
    loadA(0);

    for (int i = 0; i < NCH; i++){
        __syncthreads();                         // retire MMA(i-1) reads
        storeA(i);                               // A(i) regs -> slot i&1
        if (i + 1 < NCH){
            loadB(i+1, (i+1)*KC);                // cp.async into slot (i+1)&1
            loadA((i+1)*KC);                     // global fp32 -> regs (hidden by MMA)
            cp_wait1();                          // B(i) arrived (B(i+1) pending)
        } else {
            cp_wait0();
        }
        __syncthreads();                         // A(i) stores + B(i) visible

        const uint32_t stg = smb + (i&1)*STG_BYTES;
        const uint32_t A0 = stg, A1 = stg + ARRB, B0 = stg + 2*ARRB, B1 = stg + 3*ARRB;

        #pragma unroll
        for (int kk = 0; kk < 2; kk++){
            uint32_t ah[2][4], al[2][4];
            #pragma unroll
            for (int t = 0; t < 2; t++){
                int row = wm*32 + t*16 + (lane & 15);
                uint32_t off = (uint32_t)row*ROWB + (lane >> 4)*16 + kk*32;
                ldsm4(ah[t], A0 + off);
                ldsm4(al[t], A1 + off);
            }
            #pragma unroll
            for (int p = 0; p < 4; p++){
                int row = wn*64 + p*16 + ((lane >> 4) & 1)*8 + (lane & 7);
                uint32_t off = (uint32_t)row*ROWB + ((lane >> 3) & 1)*16 + kk*32;
                uint32_t rh[4], rl[4];
                ldsm4(rh, B0 + off);
                ldsm4(rl, B1 + off);
                #pragma unroll
                for (int t = 0; t < 2; t++){
                    mma16816(c[t][2*p],   ah[t], rh[0], rh[1]);
                    mma16816(c[t][2*p],   ah[t], rl[0], rl[1]);
                    mma16816(c[t][2*p],   al[t], rh[0], rh[1]);
                    mma16816(c[t][2*p+1], ah[t], rh[2], rh[3]);
                    mma16816(c[t][2*p+1], ah[t], rl[2], rl[3]);
                    mma16816(c[t][2*p+1], al[t], rh[2], rh[3]);
                }
            }
        }
    }

    // epilogue: tanh + dot attn_v, reduce 4-lane groups, write partials
    float p4[4] = {0.f, 0.f, 0.f, 0.f};
    #pragma unroll
    for (int t = 0; t < 2; t++)
        #pragma unroll
        for (int j = 0; j < 8; j++)
            #pragma unroll
            for (int q = 0; q < 4; q++){
                int nloc = wn*64 + j*8 + (lane & 3)*2 + (q & 1);
                float x = c[t][j][q] + wsP[nloc];
                p4[t*2 + (q >> 1)] += tanhf(x) * vP[nloc];
            }
    #pragma unroll
    for (int q = 0; q < 4; q++){
        p4[q] += __shfl_xor_sync(0xffffffffu, p4[q], 1);
        p4[q] += __shfl_xor_sync(0xffffffffu, p4[q], 2);
    }
    // combine the 2 wn-halves via smem, then single write per row (no atomics)
    __syncthreads();
    float* red = (float*)(sm);                    // reuse stage smem (MMA done)
    if ((lane & 3) == 0){
        int rloc = wm*32 + (lane >> 2);
        if (wn == 0){
            red[rloc]      = p4[0];
            red[rloc + 8]  = p4[1];
            red[rloc + 16] = p4[2];
            red[rloc + 24] = p4[3];
        }
    }
    __syncthreads();
    if (wn == 1 && (lane & 3) == 0){
        int rloc = wm*32 + (lane >> 2);
        g_energy4[blockIdx.x][m0 + rloc]      = red[rloc]      + p4[0];
        g_energy4[blockIdx.x][m0 + rloc + 8]  = red[rloc + 8]  + p4[1];
        g_energy4[blockIdx.x][m0 + rloc + 16] = red[rloc + 16] + p4[2];
        g_energy4[blockIdx.x][m0 + rloc + 24] = red[rloc + 24] + p4[3];
    }
}

// ---------------- 5) softmax over S per batch (combines 4 partials) ------
__global__ void attn_softmax(){
    const int b = blockIdx.x, t = threadIdx.x;
    __shared__ float red[8];
    float m = -1e30f;
    for (int i = t; i < S; i += 256){
        int idx = b*S + i;
        float v = g_energy4[0][idx] + g_energy4[1][idx] + g_energy4[2][idx] + g_energy4[3][idx];
        g_energy[idx] = v;
        m = fmaxf(m, v);
    }
    #pragma unroll
    for (int o = 16; o > 0; o >>= 1) m = fmaxf(m, __shfl_xor_sync(0xffffffffu, m, o));
    if ((t & 31) == 0) red[t >> 5] = m;
    __syncthreads();
    if (t == 0){ float mm = red[0]; for (int i = 1; i < 8; i++) mm = fmaxf(mm, red[i]); red[0] = mm; }
    __syncthreads();
    m = red[0];
    __syncthreads();
    float s = 0.f;
    for (int i = t; i < S; i += 256){ float x = __expf(g_energy[b*S+i]-m); g_attn[b*S+i] = x; s += x; }
    #pragma unroll
    for (int o = 16; o > 0; o >>= 1) s += __shfl_xor_sync(0xffffffffu, s, o);
    if ((t & 31) == 0) red[t >> 5] = s;
    __syncthreads();
    if (t == 0){ float ss = 0.f; for (int i = 0; i < 8; i++) ss += red[i]; red[0] = ss; }
    __syncthreads();
    float inv = 1.f / red[0];
    for (int i = t; i < S; i += 256) g_attn[b*S+i] *= inv;
}

// ---------------- 6) context[b,e] = sum_s attn[b,s]*enc[b,s,e] -----------
__global__ void context_kernel(const float* __restrict__ enc){
    const int b = blockIdx.x, ec = blockIdx.y, sc = blockIdx.z;
    __shared__ float a_s[512];
    const int t = threadIdx.x;
    for (int i = t; i < 512; i += 256) a_s[i] = g_attn[b*S + sc*512 + i];
    __syncthreads();
    const int e = ec*256 + t;
    const float* base = enc + ((size_t)b*S + sc*512)*E + e;
    float acc = 0.f;
    #pragma unroll 4
    for (int s = 0; s < 512; s++) acc = fmaf(a_s[s], base[(size_t)s*E], acc);
    atomicAdd(&g_context[b*E + e], acc);
}

// ---------------- 7) LSTM gates GEMM -------------------------------------
__global__ __launch_bounds__(256) void gates_gemm(
        const float* __restrict__ h0,
        const float* __restrict__ w_ih,
        const float* __restrict__ w_hh,
        const float* __restrict__ b_ih,
        const float* __restrict__ b_hh){
    __shared__ float Xs[16][65];
    __shared__ float Ws[16][65];
    const int n0 = blockIdx.x * 64;
    const int tid = threadIdx.x;
    const int tx = tid & 15, ty = tid >> 4;
    float acc[4][4];
    #pragma unroll
    for (int i = 0; i < 4; i++)
        #pragma unroll
        for (int j = 0; j < 4; j++) acc[i][j] = 0.f;

    for (int k0 = 0; k0 < 1792; k0 += 16) {
        for (int i = tid; i < 64*16; i += 256){
            int m = i >> 4, kk = i & 15, k = k0 + kk;
            float xv;
            if (k < E)            xv = g_context[m*E + k];
            else if (k < E+EMBD)  xv = g_embed[m*EMBD + (k - E)];
            else                  xv = h0[m*H + (k - E - EMBD)];
            Xs[kk][m] = xv;
        }
        for (int i = tid; i < 64*16; i += 256){
            int nn = i >> 4, kk = i & 15, k = k0 + kk, n = n0 + nn;
            float wv = (k < E+EMBD) ? w_ih[(size_t)n*(E+EMBD) + k]
                                    : w_hh[(size_t)n*H + (k - E - EMBD)];
            Ws[kk][nn] = wv;
        }
        __syncthreads();
        #pragma unroll
        for (int kk = 0; kk < 16; kk++){
            float ra[4], rb[4];
            #pragma unroll
            for (int i = 0; i < 4; i++) ra[i] = Xs[kk][ty*4+i];
            #pragma unroll
            for (int j = 0; j < 4; j++) rb[j] = Ws[kk][tx*4+j];
            #pragma unroll
            for (int i = 0; i < 4; i++)
                #pragma unroll
                for (int j = 0; j < 4; j++) acc[i][j] = fmaf(ra[i], rb[j], acc[i][j]);
        }
        __syncthreads();
    }
    #pragma unroll
    for (int i = 0; i < 4; i++)
        #pragma unroll
        for (int j = 0; j < 4; j++){
            int m = ty*4+i, n = n0 + tx*4+j;
            g_gates[m*(4*H) + n] = acc[i][j] + b_ih[n] + b_hh[n];
        }
}

// ---------------- 8) LSTM pointwise --------------------------------------
__global__ void lstm_kernel(const float* __restrict__ c0, float* __restrict__ out){
    const int b = blockIdx.x, h = threadIdx.x;
    const float* g = g_gates + b*(4*H);
    float ig = sigf(g[h]);
    float fg = sigf(g[H + h]);
    float gg = tanhf(g[2*H + h]);
    float og = sigf(g[3*H + h]);
    float c  = fg * c0[b*H + h] + ig * gg;
    float ht = og * tanhf(c);
    out[OUT_HT + b*H + h] = ht;
    out[OUT_CT + b*H + h] = c;
}

// ---------------- 9) logits = h_t @ v_w.T + v_b --------------------------
__global__ __launch_bounds__(256) void logits_gemm(
        const float* __restrict__ ht,
        const float* __restrict__ v_w,
        const float* __restrict__ v_b){
    __shared__ float Hs[32][64];
    __shared__ float Vs[32][128];
    const int v0 = blockIdx.x * 128;
    const int tid = threadIdx.x;
    const int tx = tid & 15, ty = tid >> 4;
    float acc[4][8];
    #pragma unroll
    for (int i = 0; i < 4; i++)
        #pragma unroll
        for (int j = 0; j < 8; j++) acc[i][j] = 0.f;

    for (int k0 = 0; k0 < H; k0 += 32) {
        for (int fl = tid; fl < 512; fl += 256){
            int m = fl >> 3, kq = (fl & 7) << 2;
            float4 hv = *(const float4*)(ht + (size_t)m*H + k0 + kq);
            Hs[kq+0][m]=hv.x; Hs[kq+1][m]=hv.y; Hs[kq+2][m]=hv.z; Hs[kq+3][m]=hv.w;
        }
        for (int fl = tid; fl < 1024; fl += 256){
            int vr = fl >> 3, kq = (fl & 7) << 2;
            int v = v0 + vr;
            float4 wv = make_float4(0.f,0.f,0.f,0.f);
            if (v < V) wv = *(const float4*)(v_w + (size_t)v*H + k0 + kq);
            Vs[kq+0][vr]=wv.x; Vs[kq+1][vr]=wv.y; Vs[kq+2][vr]=wv.z; Vs[kq+3][vr]=wv.w;
        }
        __syncthreads();
        #pragma unroll
        for (int kk = 0; kk < 32; kk++){
            float4 a0 = *(const float4*)(&Hs[kk][ty*4]);
            float4 b0 = *(const float4*)(&Vs[kk][tx*8]);
            float4 b1 = *(const float4*)(&Vs[kk][tx*8+4]);
            float ra[4] = {a0.x,a0.y,a0.z,a0.w};
            float rb[8] = {b0.x,b0.y,b0.z,b0.w,b1.x,b1.y,b1.z,b1.w};
            #pragma unroll
            for (int i = 0; i < 4; i++)
                #pragma unroll
                for (int j = 0; j < 8; j++) acc[i][j] = fmaf(ra[i], rb[j], acc[i][j]);
        }
        __syncthreads();
    }
    #pragma unroll
    for (int i = 0; i < 4; i++)
        #pragma unroll
        for (int j = 0; j < 8; j++){
            int m = ty*4+i, v = v0 + tx*8+j;
            if (v < V) g_logits[(size_t)m*V + v] = acc[i][j] + v_b[v];
        }
}

// ---------------- 10) p_gen ----------------------------------------------
__global__ void pgen_kernel(const float* __restrict__ ht,
                            const float* __restrict__ wh_vec,
                            const float* __restrict__ ws_vec,
                            const float* __restrict__ wx_vec){
    const int b = blockIdx.x, t = threadIdx.x;
    __shared__ float red[8];
    float acc = 0.f;
    for (int i = t; i < E;    i += 256) acc += g_context[b*E + i]   * wh_vec[i];
    for (int i = t; i < H;    i += 256) acc += ht[b*H + i]          * ws_vec[i];
    for (int i = t; i < EMBD; i += 256) acc += g_embed[b*EMBD + i]  * wx_vec[i];
    #pragma unroll
    for (int o = 16; o > 0; o >>= 1) acc += __shfl_xor_sync(0xffffffffu, acc, o);
    if ((t & 31) == 0) red[t >> 5] = acc;
    __syncthreads();
    if (t == 0){
        float s = 0.f;
        for (int i = 0; i < 8; i++) s += red[i];
        g_pgen[b] = sigf(s);
    }
}

// ---------------- 11) vocab softmax * p_gen -> out -----------------------
__global__ void vocab_out_kernel(float* __restrict__ out){
    const int b = blockIdx.x, t = threadIdx.x;
    __shared__ float red[16];
    const float* row = g_logits + (size_t)b*V;
    float m = -1e30f;
    for (int v = t; v < V; v += 512) m = fmaxf(m, row[v]);
    #pragma unroll
    for (int o = 16; o > 0; o >>= 1) m = fmaxf(m, __shfl_xor_sync(0xffffffffu, m, o));
    if ((t & 31) == 0) red[t >> 5] = m;
    __syncthreads();
    if (t == 0){ float mm = red[0]; for (int i = 1; i < 16; i++) mm = fmaxf(mm, red[i]); red[0] = mm; }
    __syncthreads();
    m = red[0];
    __syncthreads();
    float s = 0.f;
    for (int v = t; v < V; v += 512) s += __expf(row[v]-m);
    #pragma unroll
    for (int o = 16; o > 0; o >>= 1) s += __shfl_xor_sync(0xffffffffu, s, o);
    if ((t & 31) == 0) red[t >> 5] = s;
    __syncthreads();
    if (t == 0){ float ss = 0.f; for (int i = 0; i < 16; i++) ss += red[i]; red[0] = ss; }
    __syncthreads();
    const float scale = g_pgen[b] / red[0];
    for (int v = t; v < V; v += 512) out[(size_t)b*V + v] = __expf(row[v]-m) * scale;
}

// ---------------- 12) copy-mechanism scatter -----------------------------
__global__ void scatter_kernel(const int* __restrict__ enc_inputs,
                               float* __restrict__ out){
    const int idx = blockIdx.x*256 + threadIdx.x;
    if (idx >= MTOT) return;
    const int b = idx >> 11;
    const int tok = enc_inputs[idx];
    atomicAdd(&out[(size_t)b*V + tok], (1.f - g_pgen[b]) * g_attn[idx]);
}

// ---------------- launch --------------------------------------------------
extern "C" void kernel_launch(void* const* d_in, const int* in_sizes, int n_in,
                              void* d_out, int out_size) {
    const float* enc_out   = (const float*)d_in[0];
    const float* h0        = (const float*)d_in[1];
    const float* c0        = (const float*)d_in[2];
    const int*   dec_input = (const int*)  d_in[3];
    const int*   enc_inputs= (const int*)  d_in[4];
    const float* embed_tab = (const float*)d_in[5];
    const float* attn_wh_w = (const float*)d_in[6];
    const float* attn_wh_b = (const float*)d_in[7];
    const float* attn_ws_w = (const float*)d_in[8];
    const float* attn_ws_b = (const float*)d_in[9];
    const float* attn_v    = (const float*)d_in[10];
    const float* lstm_w_ih = (const float*)d_in[11];
    const float* lstm_w_hh = (const float*)d_in[12];
    const float* lstm_b_ih = (const float*)d_in[13];
    const float* lstm_b_hh = (const float*)d_in[14];
    const float* wh_vec    = (const float*)d_in[15];
    const float* ws_vec    = (const float*)d_in[16];
    const float* wx_vec    = (const float*)d_in[17];
    const float* v_w       = (const float*)d_in[18];
    const float* v_b       = (const float*)d_in[19];
    float* out = (float*)d_out;
    const float* ht = out + OUT_HT;

    static bool attr_set = false;
    if (!attr_set){
        cudaFuncSetAttribute(energy_mma, cudaFuncAttributeMaxDynamicSharedMemorySize, EN_SMEM);
        attr_set = true;
    }

    zero_kernel<<<256, 256>>>();
    conv_w_kernel<<<2048, 256>>>(attn_wh_w);
    wsapp_kernel<<<dim3(B, 64), 256>>>(h0, attn_ws_w, attn_ws_b, attn_wh_b);
    embed_kernel<<<B, 256>>>(dec_input, embed_tab);
    energy_mma<<<dim3(H/NTILE, MTOT/MT), 256, EN_SMEM>>>(enc_out, attn_v);
    attn_softmax<<<B, 256>>>();
    context_kernel<<<dim3(B, 4, 4), 256>>>(enc_out);
    gates_gemm<<<(4*H)/64, 256>>>(h0, lstm_w_ih, lstm_w_hh, lstm_b_ih, lstm_b_hh);
    lstm_kernel<<<B, 512>>>(c0, out);
    logits_gemm<<<(V + 127)/128, 256>>>(ht, v_w, v_b);
    pgen_kernel<<<B, 256>>>(ht, wh_vec, ws_vec, wx_vec);
    vocab_out_kernel<<<B, 512>>>(out);
    scatter_kernel<<<(MTOT + 255)/256, 256>>>(enc_inputs, out);
}